// round 14
// baseline (speedup 1.0000x reference)
#include <cuda_runtime.h>
#include <cuda_fp16.h>
#include <math.h>
#include <float.h>

#define NNODES 100000
#define NEDGES 1600000
#define NFEAT 128
#define NHID 64
#define NCLASS 40
#define NL 6
#define NB_MAX 128   // ceil(NNODES/1024) = 98

// weight-fragment table offsets (uints)
#define WF_W1   0          // K=128 -> 128*32 = 4096 uints
#define WF_WM   4096       // 6 x (64*32=2048)
#define WF_W2   16384      // K=64, padded M=64 -> 2048
#define WF_TOTAL 18432

// ---------------- device scratch (no allocations allowed) ----------------
struct __align__(8) Edge { int col; float val; };

__device__ __align__(128) __half2 g_bufA[(size_t)NNODES * NHID / 2];   // activations fp16
__device__ __align__(128) __half2 g_bufB[(size_t)NNODES * NHID / 2];
__device__ __align__(128) __half2 g_supph[(size_t)NNODES * NHID / 2];  // fp16 supp (final layer)
__device__ __align__(128) char2   g_suppq[(size_t)NNODES * NHID / 2];  // int8 supp (layers 1..7)
__device__ __align__(128) float   g_sscale[NNODES];                    // per-row dequant scale
__device__ __align__(128) __half2 g_xh[(size_t)NNODES * NFEAT / 2];    // fp16 copy of x
__device__ __align__(128) unsigned g_wfrag[WF_TOTAL];                  // mma B fragments
__device__ int   g_rowptr[NNODES + 1];
__device__ int   g_cnt[NNODES];          // histogram, then scatter cursor
__device__ Edge  g_edge[NEDGES];         // CSR-permuted (col,val) pairs
__device__ int   g_bsum[NB_MAX];
__device__ int   g_boff[NB_MAX];

// ---------------- packed f32x2 helpers (SpMM accumulate) ----------------
__device__ __forceinline__ unsigned long long ffma2(unsigned long long a,
                                                    unsigned long long b,
                                                    unsigned long long c) {
    unsigned long long d;
    asm("fma.rn.f32x2 %0, %1, %2, %3;" : "=l"(d) : "l"(a), "l"(b), "l"(c));
    return d;
}
__device__ __forceinline__ unsigned long long pack2(float x) {
    unsigned long long r;
    asm("mov.b64 %0, {%1, %1};" : "=l"(r) : "f"(x));
    return r;
}
__device__ __forceinline__ unsigned long long packf2(float2 f) {
    unsigned long long r;
    asm("mov.b64 %0, {%1, %2};" : "=l"(r) : "f"(f.x), "f"(f.y));
    return r;
}
__device__ __forceinline__ float2 unpack2(unsigned long long a) {
    float2 f;
    asm("mov.b64 {%0, %1}, %2;" : "=f"(f.x), "=f"(f.y) : "l"(a));
    return f;
}

// ---------------- fused front kernel: edge histogram + x->fp16 + wfrag build --------
__global__ void front_kernel(const int* __restrict__ row, int E,
                             const float* __restrict__ x, __half2* __restrict__ xh, int n2,
                             const float* __restrict__ W1, const float* __restrict__ Wm,
                             const float* __restrict__ W2) {
    int i = blockIdx.x * blockDim.x + threadIdx.x;
    if (i < n2) {
        float2 f = reinterpret_cast<const float2*>(x)[i];
        xh[i] = __floats2half2_rn(f.x, f.y);
    }
    if (i < E) atomicAdd(&g_cnt[row[i]], 1);
    if (i < WF_TOTAL) {
        const float* src;
        int u, Mreal;
        if (i < WF_WM)      { src = W1;                           u = i;           Mreal = NHID; }
        else if (i < WF_W2) { int j = i - WF_WM;
                              src = Wm + (j >> 11) * NHID * NHID; u = j & 2047;    Mreal = NHID; }
        else                { src = W2;                           u = i - WF_W2;   Mreal = NCLASS; }
        int half = u & 1;
        int nb   = (u >> 1) & 7;
        int lane = (u >> 4) & 31;
        int ks   = u >> 9;
        int n = nb * 8 + (lane >> 2);
        int k = ks * 16 + half * 8 + (lane & 3) * 2;
        float v0 = (n < Mreal) ? src[(size_t)k * Mreal + n]       : 0.f;
        float v1 = (n < Mreal) ? src[(size_t)(k + 1) * Mreal + n] : 0.f;
        __half2 h = __floats2half2_rn(v0, v1);
        g_wfrag[i] = *reinterpret_cast<unsigned*>(&h);
    }
}

__global__ void blockscan_kernel(int N) {
    __shared__ int ws[32];
    int tid = threadIdx.x;
    int i = blockIdx.x * 1024 + tid;
    int v = (i < N) ? g_cnt[i] : 0;
    int x = v;
    #pragma unroll
    for (int off = 1; off < 32; off <<= 1) {
        int y = __shfl_up_sync(0xFFFFFFFFu, x, off);
        if ((tid & 31) >= off) x += y;
    }
    if ((tid & 31) == 31) ws[tid >> 5] = x;
    __syncthreads();
    if (tid < 32) {
        int w = ws[tid];
        int xw = w;
        #pragma unroll
        for (int off = 1; off < 32; off <<= 1) {
            int y = __shfl_up_sync(0xFFFFFFFFu, xw, off);
            if (tid >= off) xw += y;
        }
        ws[tid] = xw - w;
        if (tid == 31) g_bsum[blockIdx.x] = xw;
    }
    __syncthreads();
    if (i < N) g_rowptr[i] = ws[tid >> 5] + (x - v);
}

__global__ void bsum_scan_kernel(int NB, int N) {
    __shared__ int ws[4];
    int tid = threadIdx.x;   // 128 threads
    int v = (tid < NB) ? g_bsum[tid] : 0;
    int x = v;
    #pragma unroll
    for (int off = 1; off < 32; off <<= 1) {
        int y = __shfl_up_sync(0xFFFFFFFFu, x, off);
        if ((tid & 31) >= off) x += y;
    }
    if ((tid & 31) == 31) ws[tid >> 5] = x;
    __syncthreads();
    int off4 = 0;
    #pragma unroll
    for (int w = 0; w < 3; w++)
        if (w < (tid >> 5)) off4 += ws[w];
    if (tid < NB) g_boff[tid] = off4 + x - v;
    if (tid == 127) g_rowptr[N] = off4 + x;
}

__global__ void addoff_kernel(int N) {
    int i = blockIdx.x * blockDim.x + threadIdx.x;
    if (i < N) {
        int r = g_rowptr[i] + g_boff[i >> 10];
        g_rowptr[i] = r;
        g_cnt[i] = r;
    }
}

__global__ void scatter_kernel(const int* __restrict__ row, const int* __restrict__ col,
                               const float* __restrict__ val, int E) {
    int e = blockIdx.x * blockDim.x + threadIdx.x;
    if (e < E) {
        int r = row[e];
        int p = atomicAdd(&g_cnt[r], 1);
        Edge ed; ed.col = col[e]; ed.val = val[e];
        g_edge[p] = ed;
    }
}

// ---------------- tensor-core GEMM: H[N,K](fp16) @ Wfrag -> int8+scale OR fp16 -------
// No shared memory, no syncthreads. 8 warps/CTA, 32 rows/warp -> 256 rows/CTA.
// QUANT=true: per-row symmetric int8 quantization (char2 rows + float scale).
// QUANT=false: fp16 half2 rows (stride 32 half2).
template <int K, int NB, bool QUANT>
__launch_bounds__(256)
__global__ void hgemm_kernel(const __half* __restrict__ H, const unsigned* __restrict__ frag,
                             __half2* __restrict__ outh, char2* __restrict__ outq,
                             float* __restrict__ oscale, int N) {
    const int warp = threadIdx.x >> 5;
    const int lane = threadIdx.x & 31;
    const int kc = (lane & 3) * 2;
    const int row0 = blockIdx.x * 256 + warp * 32;

    const __half* pA[2];
    const __half* pB[2];
    int rA[2], rB[2];
    #pragma unroll
    for (int t = 0; t < 2; t++) {
        rA[t] = row0 + t * 16 + (lane >> 2);
        rB[t] = rA[t] + 8;
        pA[t] = H + (size_t)min(rA[t], N - 1) * K;
        pB[t] = H + (size_t)min(rB[t], N - 1) * K;
    }

    float c[2][NB][4];
    #pragma unroll
    for (int t = 0; t < 2; t++)
        #pragma unroll
        for (int nb = 0; nb < NB; nb++)
            #pragma unroll
            for (int q = 0; q < 4; q++) c[t][nb][q] = 0.f;

    #pragma unroll 1
    for (int h0 = 0; h0 < K; h0 += 32) {
        unsigned bf[2][NB][2];
        #pragma unroll
        for (int ks2 = 0; ks2 < 2; ks2++) {
            int ks = (h0 >> 4) + ks2;
            const uint4* fr = reinterpret_cast<const uint4*>(frag + (size_t)(ks * 32 + lane) * (NB * 2));
            #pragma unroll
            for (int q = 0; q < NB / 2; q++) {
                uint4 v = __ldg(fr + q);
                bf[ks2][q * 2 + 0][0] = v.x;
                bf[ks2][q * 2 + 0][1] = v.y;
                bf[ks2][q * 2 + 1][0] = v.z;
                bf[ks2][q * 2 + 1][1] = v.w;
            }
        }
        #pragma unroll
        for (int ks2 = 0; ks2 < 2; ks2++) {
            const int k0 = h0 + ks2 * 16;
            #pragma unroll
            for (int t = 0; t < 2; t++) {
                unsigned a0 = *reinterpret_cast<const unsigned*>(pA[t] + k0 + kc);
                unsigned a1 = *reinterpret_cast<const unsigned*>(pB[t] + k0 + kc);
                unsigned a2 = *reinterpret_cast<const unsigned*>(pA[t] + k0 + kc + 8);
                unsigned a3 = *reinterpret_cast<const unsigned*>(pB[t] + k0 + kc + 8);
                #pragma unroll
                for (int nb = 0; nb < NB; nb++) {
                    asm volatile(
                        "mma.sync.aligned.m16n8k16.row.col.f32.f16.f16.f32 "
                        "{%0,%1,%2,%3}, {%4,%5,%6,%7}, {%8,%9}, {%0,%1,%2,%3};"
                        : "+f"(c[t][nb][0]), "+f"(c[t][nb][1]), "+f"(c[t][nb][2]), "+f"(c[t][nb][3])
                        : "r"(a0), "r"(a1), "r"(a2), "r"(a3),
                          "r"(bf[ks2][nb][0]), "r"(bf[ks2][nb][1]));
                }
            }
        }
    }

    const int colh = (lane & 3);
    if (QUANT) {
        #pragma unroll
        for (int t = 0; t < 2; t++) {
            // per-row absmax: local over nb, then across the 4-lane quad
            float ma = 0.f, mb = 0.f;
            #pragma unroll
            for (int nb = 0; nb < NB; nb++) {
                ma = fmaxf(ma, fmaxf(fabsf(c[t][nb][0]), fabsf(c[t][nb][1])));
                mb = fmaxf(mb, fmaxf(fabsf(c[t][nb][2]), fabsf(c[t][nb][3])));
            }
            ma = fmaxf(ma, __shfl_xor_sync(0xFFFFFFFFu, ma, 1));
            ma = fmaxf(ma, __shfl_xor_sync(0xFFFFFFFFu, ma, 2));
            mb = fmaxf(mb, __shfl_xor_sync(0xFFFFFFFFu, mb, 1));
            mb = fmaxf(mb, __shfl_xor_sync(0xFFFFFFFFu, mb, 2));
            float sA = ma * (1.f / 127.f);
            float sB = mb * (1.f / 127.f);
            float iA = (ma > 0.f) ? 127.f / ma : 0.f;
            float iB = (mb > 0.f) ? 127.f / mb : 0.f;
            #pragma unroll
            for (int nb = 0; nb < NB; nb++) {
                int cidx = nb * 4 + colh;
                if (rA[t] < N) {
                    char2 qa;
                    qa.x = (char)__float2int_rn(c[t][nb][0] * iA);
                    qa.y = (char)__float2int_rn(c[t][nb][1] * iA);
                    outq[(size_t)rA[t] * 32 + cidx] = qa;
                }
                if (rB[t] < N) {
                    char2 qb;
                    qb.x = (char)__float2int_rn(c[t][nb][2] * iB);
                    qb.y = (char)__float2int_rn(c[t][nb][3] * iB);
                    outq[(size_t)rB[t] * 32 + cidx] = qb;
                }
            }
            if (colh == 0) {
                if (rA[t] < N) oscale[rA[t]] = sA;
                if (rB[t] < N) oscale[rB[t]] = sB;
            }
        }
    } else {
        #pragma unroll
        for (int t = 0; t < 2; t++) {
            #pragma unroll
            for (int nb = 0; nb < NB; nb++) {
                int cidx = nb * 4 + colh;
                if (rA[t] < N) outh[(size_t)rA[t] * (NB * 4) + cidx] = __floats2half2_rn(c[t][nb][0], c[t][nb][1]);
                if (rB[t] < N) outh[(size_t)rB[t] * (NB * 4) + cidx] = __floats2half2_rn(c[t][nb][2], c[t][nb][3]);
            }
        }
    }
}

// ---------------- fused SpMM over int8 supp + per-row scale + epilogue ----------------
// One warp per row; all 32 lanes active (M = 64 cols = 32 char2).
// MODE 0: out(fp16) = relu(agg + bias)
// MODE 1: out(fp16) = relu(agg + bias) + res(fp16)   (out may alias res)
template <int MODE>
__launch_bounds__(256)
__global__ void spmm_q_kernel(const char2* __restrict__ suppq, const float* __restrict__ sscale,
                              const float* __restrict__ bias, const __half2* __restrict__ res,
                              __half2* __restrict__ out, int N) {
    int warp = (blockIdx.x * blockDim.x + threadIdx.x) >> 5;
    int lane = threadIdx.x & 31;
    if (warp >= N) return;

    int start = g_rowptr[warp];
    int end   = g_rowptr[warp + 1];
    unsigned long long acc = 0ull;

    int e = start;
    for (; e + 8 <= end; e += 8) {
        Edge  e0 = g_edge[e],     e1 = g_edge[e + 1];
        Edge  e2 = g_edge[e + 2], e3 = g_edge[e + 3];
        Edge  e4 = g_edge[e + 4], e5 = g_edge[e + 5];
        Edge  e6 = g_edge[e + 6], e7 = g_edge[e + 7];
        float c0 = sscale[e0.col], c1 = sscale[e1.col];
        float c2 = sscale[e2.col], c3 = sscale[e3.col];
        float c4 = sscale[e4.col], c5 = sscale[e5.col];
        float c6 = sscale[e6.col], c7 = sscale[e7.col];
        char2 q0 = suppq[(size_t)e0.col * 32 + lane];
        char2 q1 = suppq[(size_t)e1.col * 32 + lane];
        char2 q2 = suppq[(size_t)e2.col * 32 + lane];
        char2 q3 = suppq[(size_t)e3.col * 32 + lane];
        char2 q4 = suppq[(size_t)e4.col * 32 + lane];
        char2 q5 = suppq[(size_t)e5.col * 32 + lane];
        char2 q6 = suppq[(size_t)e6.col * 32 + lane];
        char2 q7 = suppq[(size_t)e7.col * 32 + lane];
        acc = ffma2(pack2(e0.val * c0), packf2(make_float2((float)q0.x, (float)q0.y)), acc);
        acc = ffma2(pack2(e1.val * c1), packf2(make_float2((float)q1.x, (float)q1.y)), acc);
        acc = ffma2(pack2(e2.val * c2), packf2(make_float2((float)q2.x, (float)q2.y)), acc);
        acc = ffma2(pack2(e3.val * c3), packf2(make_float2((float)q3.x, (float)q3.y)), acc);
        acc = ffma2(pack2(e4.val * c4), packf2(make_float2((float)q4.x, (float)q4.y)), acc);
        acc = ffma2(pack2(e5.val * c5), packf2(make_float2((float)q5.x, (float)q5.y)), acc);
        acc = ffma2(pack2(e6.val * c6), packf2(make_float2((float)q6.x, (float)q6.y)), acc);
        acc = ffma2(pack2(e7.val * c7), packf2(make_float2((float)q7.x, (float)q7.y)), acc);
    }
    for (; e + 2 <= end; e += 2) {
        Edge  e0 = g_edge[e], e1 = g_edge[e + 1];
        float c0 = sscale[e0.col], c1 = sscale[e1.col];
        char2 q0 = suppq[(size_t)e0.col * 32 + lane];
        char2 q1 = suppq[(size_t)e1.col * 32 + lane];
        acc = ffma2(pack2(e0.val * c0), packf2(make_float2((float)q0.x, (float)q0.y)), acc);
        acc = ffma2(pack2(e1.val * c1), packf2(make_float2((float)q1.x, (float)q1.y)), acc);
    }
    if (e < end) {
        Edge  ed = g_edge[e];
        float cs = sscale[ed.col];
        char2 q  = suppq[(size_t)ed.col * 32 + lane];
        acc = ffma2(pack2(ed.val * cs), packf2(make_float2((float)q.x, (float)q.y)), acc);
    }

    float2 av = unpack2(acc);
    int j = lane * 2;
    float a0 = fmaxf(av.x + bias[j],     0.f);
    float a1 = fmaxf(av.y + bias[j + 1], 0.f);
    if (MODE == 1) {
        float2 r = __half22float2(res[(size_t)warp * 32 + lane]);
        a0 += r.x;
        a1 += r.y;
    }
    out[(size_t)warp * 32 + lane] = __floats2half2_rn(a0, a1);
}

// ---------------- final SpMM (fp16 supp, zero-padded to 64 cols) + log_softmax -------
__launch_bounds__(256)
__global__ void spmm_lsm_kernel(const __half2* __restrict__ supp, const float* __restrict__ bias,
                                float* __restrict__ out, int N) {
    int warp = (blockIdx.x * blockDim.x + threadIdx.x) >> 5;
    int lane = threadIdx.x & 31;
    if (warp >= N) return;

    int start = g_rowptr[warp];
    int end   = g_rowptr[warp + 1];
    unsigned long long acc = 0ull;

    int e = start;
    for (; e + 8 <= end; e += 8) {
        Edge e0 = g_edge[e],     e1 = g_edge[e + 1];
        Edge e2 = g_edge[e + 2], e3 = g_edge[e + 3];
        Edge e4 = g_edge[e + 4], e5 = g_edge[e + 5];
        Edge e6 = g_edge[e + 6], e7 = g_edge[e + 7];
        __half2 s0 = supp[(size_t)e0.col * 32 + lane];
        __half2 s1 = supp[(size_t)e1.col * 32 + lane];
        __half2 s2 = supp[(size_t)e2.col * 32 + lane];
        __half2 s3 = supp[(size_t)e3.col * 32 + lane];
        __half2 s4 = supp[(size_t)e4.col * 32 + lane];
        __half2 s5 = supp[(size_t)e5.col * 32 + lane];
        __half2 s6 = supp[(size_t)e6.col * 32 + lane];
        __half2 s7 = supp[(size_t)e7.col * 32 + lane];
        acc = ffma2(pack2(e0.val), packf2(__half22float2(s0)), acc);
        acc = ffma2(pack2(e1.val), packf2(__half22float2(s1)), acc);
        acc = ffma2(pack2(e2.val), packf2(__half22float2(s2)), acc);
        acc = ffma2(pack2(e3.val), packf2(__half22float2(s3)), acc);
        acc = ffma2(pack2(e4.val), packf2(__half22float2(s4)), acc);
        acc = ffma2(pack2(e5.val), packf2(__half22float2(s5)), acc);
        acc = ffma2(pack2(e6.val), packf2(__half22float2(s6)), acc);
        acc = ffma2(pack2(e7.val), packf2(__half22float2(s7)), acc);
    }
    for (; e + 2 <= end; e += 2) {
        Edge e0 = g_edge[e], e1 = g_edge[e + 1];
        __half2 s0 = supp[(size_t)e0.col * 32 + lane];
        __half2 s1 = supp[(size_t)e1.col * 32 + lane];
        acc = ffma2(pack2(e0.val), packf2(__half22float2(s0)), acc);
        acc = ffma2(pack2(e1.val), packf2(__half22float2(s1)), acc);
    }
    if (e < end) {
        Edge ed = g_edge[e];
        __half2 s = supp[(size_t)ed.col * 32 + lane];
        acc = ffma2(pack2(ed.val), packf2(__half22float2(s)), acc);
    }

    float2 av = unpack2(acc);
    int j = lane * 2;
    const bool active = (j < NCLASS);
    float a0 = active ? av.x + bias[j]     : -FLT_MAX;
    float a1 = active ? av.y + bias[j + 1] : -FLT_MAX;
    float m = fmaxf(a0, a1);
    #pragma unroll
    for (int off = 16; off > 0; off >>= 1)
        m = fmaxf(m, __shfl_xor_sync(0xFFFFFFFFu, m, off));
    float s = active ? (expf(a0 - m) + expf(a1 - m)) : 0.f;
    #pragma unroll
    for (int off = 16; off > 0; off >>= 1)
        s += __shfl_xor_sync(0xFFFFFFFFu, s, off);
    float ls = logf(s);
    if (active) {
        out[(size_t)warp * NCLASS + j]     = a0 - m - ls;
        out[(size_t)warp * NCLASS + j + 1] = a1 - m - ls;
    }
}

// ---------------- host launch ----------------
extern "C" void kernel_launch(void* const* d_in, const int* in_sizes, int n_in,
                              void* d_out, int out_size) {
    const float* x    = (const float*)d_in[0];
    const int*   erow = (const int*)  d_in[1];
    const int*   ecol = (const int*)  d_in[2];
    const float* eval_= (const float*)d_in[3];
    const float* W1   = (const float*)d_in[4];
    const float* b1   = (const float*)d_in[5];
    const float* Wm   = (const float*)d_in[6];
    const float* bm   = (const float*)d_in[7];
    const float* W2   = (const float*)d_in[8];
    const float* b2   = (const float*)d_in[9];

    int N = in_sizes[0] / NFEAT;
    int E = in_sizes[1];
    int NBLK = (N + 1023) / 1024;
    int n2 = N * NFEAT / 2;

    __half2 *bufA, *bufB, *supph, *xh;
    char2* suppq;
    float* sscale;
    unsigned* wfrag;
    int* cnt;
    cudaGetSymbolAddress((void**)&bufA,   g_bufA);
    cudaGetSymbolAddress((void**)&bufB,   g_bufB);
    cudaGetSymbolAddress((void**)&supph,  g_supph);
    cudaGetSymbolAddress((void**)&suppq,  g_suppq);
    cudaGetSymbolAddress((void**)&sscale, g_sscale);
    cudaGetSymbolAddress((void**)&xh,     g_xh);
    cudaGetSymbolAddress((void**)&wfrag,  g_wfrag);
    cudaGetSymbolAddress((void**)&cnt,    g_cnt);

    int gemmGrid = (N + 255) / 256;
    int spmmGrid = (N + 7) / 8;     // 8 warps (rows) per 256-thread block

    // front section
    cudaMemsetAsync(cnt, 0, (size_t)N * sizeof(int), 0);
    front_kernel<<<(n2 + 255) / 256, 256>>>(erow, E, x, xh, n2, W1, Wm, W2);
    hgemm_kernel<NFEAT, 8, true><<<gemmGrid, 256>>>((const __half*)xh, wfrag,
                                                    nullptr, suppq, sscale, N);
    blockscan_kernel<<<NBLK, 1024>>>(N);
    bsum_scan_kernel<<<1, 128>>>(NBLK, N);
    addoff_kernel<<<(N + 255) / 256, 256>>>(N);
    scatter_kernel<<<(E + 255) / 256, 256>>>(erow, ecol, eval_, E);

    // layer 1: h1 = relu(spmm(x @ W1) + b1)            -> bufA
    spmm_q_kernel<0><<<spmmGrid, 256>>>(suppq, sscale, b1, nullptr, bufA, N);

    // layer 2: h2 = relu(spmm(h1 @ Wm[0]) + bm[0])     -> bufB
    hgemm_kernel<NHID, 8, true><<<gemmGrid, 256>>>((const __half*)bufA, wfrag + WF_WM,
                                                   nullptr, suppq, sscale, N);
    spmm_q_kernel<0><<<spmmGrid, 256>>>(suppq, sscale, bm, nullptr, bufB, N);

    // middle layers k=1..NL-1: h = relu(gconv(prev)) + prev2 ; written over prev2
    __half2* prev2 = bufA;
    __half2* prev  = bufB;
    for (int k = 1; k < NL; k++) {
        hgemm_kernel<NHID, 8, true><<<gemmGrid, 256>>>((const __half*)prev,
                                                       wfrag + WF_WM + k * 2048,
                                                       nullptr, suppq, sscale, N);
        spmm_q_kernel<1><<<spmmGrid, 256>>>(suppq, sscale, bm + (size_t)k * NHID,
                                            prev2, prev2, N);
        __half2* t = prev2; prev2 = prev; prev = t;
    }

    // final: log_softmax(spmm(prev @ W2) + b2) -> d_out  (fp16 supp, zero-padded cols)
    hgemm_kernel<NHID, 8, false><<<gemmGrid, 256>>>((const __half*)prev, wfrag + WF_W2,
                                                    supph, nullptr, nullptr, N);
    spmm_lsm_kernel<<<spmmGrid, 256>>>(supph, b2, (float*)d_out, N);
}

// round 15
// speedup vs baseline: 1.1690x; 1.1690x over previous
#include <cuda_runtime.h>
#include <cuda_fp16.h>
#include <math.h>
#include <float.h>

#define NNODES 100000
#define NEDGES 1600000
#define NFEAT 128
#define NHID 64
#define NCLASS 40
#define NL 6
#define NB_MAX 128   // ceil(NNODES/1024) = 98

// weight-fragment table offsets (uints)
#define WF_W1   0          // K=128 -> 128*32 = 4096 uints
#define WF_WM   4096       // 6 x (64*32=2048)
#define WF_W2   16384      // K=64, padded M=64 -> 2048
#define WF_TOTAL 18432

// ---------------- device scratch (no allocations allowed) ----------------
// Edge: col index + edge value pre-duplicated as half2 (for HFMA2 in SpMM)
struct __align__(8) Edge { int col; __half2 val; };

__device__ __align__(128) __half2 g_bufA[(size_t)NNODES * NHID / 2];   // activations fp16
__device__ __align__(128) __half2 g_bufB[(size_t)NNODES * NHID / 2];
__device__ __align__(128) __half2 g_supph[(size_t)NNODES * NHID / 2];  // GEMM output fp16
__device__ __align__(128) __half2 g_xh[(size_t)NNODES * NFEAT / 2];    // fp16 copy of x
__device__ __align__(128) unsigned g_wfrag[WF_TOTAL];                  // mma B fragments
__device__ int   g_rowptr[NNODES + 1];
__device__ int   g_cnt[NNODES];          // histogram, then scatter cursor
__device__ Edge  g_edge[NEDGES];         // CSR-permuted (col,val) pairs
__device__ int   g_bsum[NB_MAX];
__device__ int   g_boff[NB_MAX];

// ---------------- packed f32x2 helpers ----------------
__device__ __forceinline__ unsigned long long ffma2(unsigned long long a,
                                                    unsigned long long b,
                                                    unsigned long long c) {
    unsigned long long d;
    asm("fma.rn.f32x2 %0, %1, %2, %3;" : "=l"(d) : "l"(a), "l"(b), "l"(c));
    return d;
}
__device__ __forceinline__ unsigned long long pack2(float x) {
    unsigned long long r;
    asm("mov.b64 %0, {%1, %1};" : "=l"(r) : "f"(x));
    return r;
}
__device__ __forceinline__ unsigned long long packf2(float2 f) {
    unsigned long long r;
    asm("mov.b64 %0, {%1, %2};" : "=l"(r) : "f"(f.x), "f"(f.y));
    return r;
}
__device__ __forceinline__ float2 unpack2(unsigned long long a) {
    float2 f;
    asm("mov.b64 {%0, %1}, %2;" : "=f"(f.x), "=f"(f.y) : "l"(a));
    return f;
}

// ---------------- fused front kernel: edge histogram + x->fp16 + wfrag build --------
__global__ void front_kernel(const int* __restrict__ row, int E,
                             const float* __restrict__ x, __half2* __restrict__ xh, int n2,
                             const float* __restrict__ W1, const float* __restrict__ Wm,
                             const float* __restrict__ W2) {
    int i = blockIdx.x * blockDim.x + threadIdx.x;
    if (i < n2) {
        float2 f = reinterpret_cast<const float2*>(x)[i];
        xh[i] = __floats2half2_rn(f.x, f.y);
    }
    if (i < E) atomicAdd(&g_cnt[row[i]], 1);
    if (i < WF_TOTAL) {
        const float* src;
        int u, Mreal;
        if (i < WF_WM)      { src = W1;                           u = i;           Mreal = NHID; }
        else if (i < WF_W2) { int j = i - WF_WM;
                              src = Wm + (j >> 11) * NHID * NHID; u = j & 2047;    Mreal = NHID; }
        else                { src = W2;                           u = i - WF_W2;   Mreal = NCLASS; }
        int half = u & 1;
        int nb   = (u >> 1) & 7;
        int lane = (u >> 4) & 31;
        int ks   = u >> 9;
        int n = nb * 8 + (lane >> 2);
        int k = ks * 16 + half * 8 + (lane & 3) * 2;
        float v0 = (n < Mreal) ? src[(size_t)k * Mreal + n]       : 0.f;
        float v1 = (n < Mreal) ? src[(size_t)(k + 1) * Mreal + n] : 0.f;
        __half2 h = __floats2half2_rn(v0, v1);
        g_wfrag[i] = *reinterpret_cast<unsigned*>(&h);
    }
}

__global__ void blockscan_kernel(int N) {
    __shared__ int ws[32];
    int tid = threadIdx.x;
    int i = blockIdx.x * 1024 + tid;
    int v = (i < N) ? g_cnt[i] : 0;
    int x = v;
    #pragma unroll
    for (int off = 1; off < 32; off <<= 1) {
        int y = __shfl_up_sync(0xFFFFFFFFu, x, off);
        if ((tid & 31) >= off) x += y;
    }
    if ((tid & 31) == 31) ws[tid >> 5] = x;
    __syncthreads();
    if (tid < 32) {
        int w = ws[tid];
        int xw = w;
        #pragma unroll
        for (int off = 1; off < 32; off <<= 1) {
            int y = __shfl_up_sync(0xFFFFFFFFu, xw, off);
            if (tid >= off) xw += y;
        }
        ws[tid] = xw - w;
        if (tid == 31) g_bsum[blockIdx.x] = xw;
    }
    __syncthreads();
    if (i < N) g_rowptr[i] = ws[tid >> 5] + (x - v);
}

__global__ void bsum_scan_kernel(int NB, int N) {
    __shared__ int ws[4];
    int tid = threadIdx.x;   // 128 threads
    int v = (tid < NB) ? g_bsum[tid] : 0;
    int x = v;
    #pragma unroll
    for (int off = 1; off < 32; off <<= 1) {
        int y = __shfl_up_sync(0xFFFFFFFFu, x, off);
        if ((tid & 31) >= off) x += y;
    }
    if ((tid & 31) == 31) ws[tid >> 5] = x;
    __syncthreads();
    int off4 = 0;
    #pragma unroll
    for (int w = 0; w < 3; w++)
        if (w < (tid >> 5)) off4 += ws[w];
    if (tid < NB) g_boff[tid] = off4 + x - v;
    if (tid == 127) g_rowptr[N] = off4 + x;
}

__global__ void addoff_kernel(int N) {
    int i = blockIdx.x * blockDim.x + threadIdx.x;
    if (i < N) {
        int r = g_rowptr[i] + g_boff[i >> 10];
        g_rowptr[i] = r;
        g_cnt[i] = r;
    }
}

__global__ void scatter_kernel(const int* __restrict__ row, const int* __restrict__ col,
                               const float* __restrict__ val, int E) {
    int e = blockIdx.x * blockDim.x + threadIdx.x;
    if (e < E) {
        int r = row[e];
        int p = atomicAdd(&g_cnt[r], 1);
        float v = val[e];
        Edge ed; ed.col = col[e]; ed.val = __floats2half2_rn(v, v);
        g_edge[p] = ed;
    }
}

// ---------------- tensor-core GEMM: out[N,NB*8](fp16) = H[N,K](fp16) @ Wfrag ----------
// No shared memory, no syncthreads. B fragments read from the precomputed global
// table (L1/L2-hot). 8 warps/CTA, 32 rows/warp (two m16 tiles) -> 256 rows/CTA.
template <int K, int NB>
__launch_bounds__(256)
__global__ void hgemm_kernel(const __half* __restrict__ H, const unsigned* __restrict__ frag,
                             __half2* __restrict__ out, int N) {
    const int warp = threadIdx.x >> 5;
    const int lane = threadIdx.x & 31;
    const int kc = (lane & 3) * 2;
    const int row0 = blockIdx.x * 256 + warp * 32;

    const __half* pA[2];
    const __half* pB[2];
    int rA[2], rB[2];
    #pragma unroll
    for (int t = 0; t < 2; t++) {
        rA[t] = row0 + t * 16 + (lane >> 2);
        rB[t] = rA[t] + 8;
        pA[t] = H + (size_t)min(rA[t], N - 1) * K;
        pB[t] = H + (size_t)min(rB[t], N - 1) * K;
    }

    float c[2][NB][4];
    #pragma unroll
    for (int t = 0; t < 2; t++)
        #pragma unroll
        for (int nb = 0; nb < NB; nb++)
            #pragma unroll
            for (int q = 0; q < 4; q++) c[t][nb][q] = 0.f;

    #pragma unroll 1
    for (int h0 = 0; h0 < K; h0 += 32) {
        unsigned bf[2][NB][2];
        #pragma unroll
        for (int ks2 = 0; ks2 < 2; ks2++) {
            int ks = (h0 >> 4) + ks2;
            const uint4* fr = reinterpret_cast<const uint4*>(frag + (size_t)(ks * 32 + lane) * (NB * 2));
            #pragma unroll
            for (int q = 0; q < NB / 2; q++) {
                uint4 v = __ldg(fr + q);
                bf[ks2][q * 2 + 0][0] = v.x;
                bf[ks2][q * 2 + 0][1] = v.y;
                bf[ks2][q * 2 + 1][0] = v.z;
                bf[ks2][q * 2 + 1][1] = v.w;
            }
        }
        #pragma unroll
        for (int ks2 = 0; ks2 < 2; ks2++) {
            const int k0 = h0 + ks2 * 16;
            #pragma unroll
            for (int t = 0; t < 2; t++) {
                unsigned a0 = *reinterpret_cast<const unsigned*>(pA[t] + k0 + kc);
                unsigned a1 = *reinterpret_cast<const unsigned*>(pB[t] + k0 + kc);
                unsigned a2 = *reinterpret_cast<const unsigned*>(pA[t] + k0 + kc + 8);
                unsigned a3 = *reinterpret_cast<const unsigned*>(pB[t] + k0 + kc + 8);
                #pragma unroll
                for (int nb = 0; nb < NB; nb++) {
                    asm volatile(
                        "mma.sync.aligned.m16n8k16.row.col.f32.f16.f16.f32 "
                        "{%0,%1,%2,%3}, {%4,%5,%6,%7}, {%8,%9}, {%0,%1,%2,%3};"
                        : "+f"(c[t][nb][0]), "+f"(c[t][nb][1]), "+f"(c[t][nb][2]), "+f"(c[t][nb][3])
                        : "r"(a0), "r"(a1), "r"(a2), "r"(a3),
                          "r"(bf[ks2][nb][0]), "r"(bf[ks2][nb][1]));
                }
            }
        }
    }

    const int colh = (lane & 3);
    #pragma unroll
    for (int t = 0; t < 2; t++) {
        #pragma unroll
        for (int nb = 0; nb < NB; nb++) {
            int cidx = nb * 4 + colh;
            if (rA[t] < N) out[(size_t)rA[t] * (NB * 4) + cidx] = __floats2half2_rn(c[t][nb][0], c[t][nb][1]);
            if (rB[t] < N) out[(size_t)rB[t] * (NB * 4) + cidx] = __floats2half2_rn(c[t][nb][2], c[t][nb][3]);
        }
    }
}

// ---------------- fused SpMM (gather form, fp16 supp, HFMA2 batches) + epilogue -------
// All 32 lanes gather (supp rows are 64 cols = 32 half2; zero-padded for final layer).
// Per 8-edge batch: fp16 HFMA2 accumulation, folded into an f32x2 master.
// MODE 0: out(fp16) = relu(agg + bias)
// MODE 1: out(fp16) = relu(agg + bias) + res(fp16)   (out may alias res)
// MODE 2: out(fp32) = log_softmax(agg + bias)        (M = NCLASS)
template <int M, int MODE>
__launch_bounds__(256)
__global__ void spmm_kernel(const __half2* __restrict__ supp, const float* __restrict__ bias,
                            const __half2* __restrict__ res, void* __restrict__ outv, int N) {
    int warp = (blockIdx.x * blockDim.x + threadIdx.x) >> 5;
    int lane = threadIdx.x & 31;
    if (warp >= N) return;

    int start = g_rowptr[warp];
    int end   = g_rowptr[warp + 1];
    unsigned long long accm = 0ull;              // f32x2 master accumulator
    const unsigned long long one2 = pack2(1.f);

    int e = start;
    for (; e + 8 <= end; e += 8) {
        Edge e0 = g_edge[e],     e1 = g_edge[e + 1];
        Edge e2 = g_edge[e + 2], e3 = g_edge[e + 3];
        Edge e4 = g_edge[e + 4], e5 = g_edge[e + 5];
        Edge e6 = g_edge[e + 6], e7 = g_edge[e + 7];
        __half2 s0 = supp[(size_t)e0.col * 32 + lane];
        __half2 s1 = supp[(size_t)e1.col * 32 + lane];
        __half2 s2 = supp[(size_t)e2.col * 32 + lane];
        __half2 s3 = supp[(size_t)e3.col * 32 + lane];
        __half2 s4 = supp[(size_t)e4.col * 32 + lane];
        __half2 s5 = supp[(size_t)e5.col * 32 + lane];
        __half2 s6 = supp[(size_t)e6.col * 32 + lane];
        __half2 s7 = supp[(size_t)e7.col * 32 + lane];
        __half2 ah = __hmul2(e0.val, s0);
        ah = __hfma2(e1.val, s1, ah);
        ah = __hfma2(e2.val, s2, ah);
        ah = __hfma2(e3.val, s3, ah);
        ah = __hfma2(e4.val, s4, ah);
        ah = __hfma2(e5.val, s5, ah);
        ah = __hfma2(e6.val, s6, ah);
        ah = __hfma2(e7.val, s7, ah);
        accm = ffma2(one2, packf2(__half22float2(ah)), accm);
    }
    for (; e + 2 <= end; e += 2) {
        Edge e0 = g_edge[e], e1 = g_edge[e + 1];
        __half2 s0 = supp[(size_t)e0.col * 32 + lane];
        __half2 s1 = supp[(size_t)e1.col * 32 + lane];
        __half2 ah = __hmul2(e0.val, s0);
        ah = __hfma2(e1.val, s1, ah);
        accm = ffma2(one2, packf2(__half22float2(ah)), accm);
    }
    if (e < end) {
        Edge ed = g_edge[e];
        __half2 s = supp[(size_t)ed.col * 32 + lane];
        __half2 ah = __hmul2(ed.val, s);
        accm = ffma2(one2, packf2(__half22float2(ah)), accm);
    }

    float2 av = unpack2(accm);
    int j = lane * 2;
    const bool active = (j < M);

    if (MODE == 2) {
        float* out = (float*)outv;
        float a0 = active ? av.x + bias[j]     : -FLT_MAX;
        float a1 = active ? av.y + bias[j + 1] : -FLT_MAX;
        float m = fmaxf(a0, a1);
        #pragma unroll
        for (int off = 16; off > 0; off >>= 1)
            m = fmaxf(m, __shfl_xor_sync(0xFFFFFFFFu, m, off));
        float s = active ? (expf(a0 - m) + expf(a1 - m)) : 0.f;
        #pragma unroll
        for (int off = 16; off > 0; off >>= 1)
            s += __shfl_xor_sync(0xFFFFFFFFu, s, off);
        float ls = logf(s);
        if (active) {
            out[(size_t)warp * M + j]     = a0 - m - ls;
            out[(size_t)warp * M + j + 1] = a1 - m - ls;
        }
    } else {
        __half2* out = (__half2*)outv;
        float a0 = fmaxf(av.x + bias[j],     0.f);
        float a1 = fmaxf(av.y + bias[j + 1], 0.f);
        if (MODE == 1) {
            float2 r = __half22float2(res[(size_t)warp * 32 + lane]);
            a0 += r.x;
            a1 += r.y;
        }
        out[(size_t)warp * 32 + lane] = __floats2half2_rn(a0, a1);
    }
}

// ---------------- host launch ----------------
extern "C" void kernel_launch(void* const* d_in, const int* in_sizes, int n_in,
                              void* d_out, int out_size) {
    const float* x    = (const float*)d_in[0];
    const int*   erow = (const int*)  d_in[1];
    const int*   ecol = (const int*)  d_in[2];
    const float* eval_= (const float*)d_in[3];
    const float* W1   = (const float*)d_in[4];
    const float* b1   = (const float*)d_in[5];
    const float* Wm   = (const float*)d_in[6];
    const float* bm   = (const float*)d_in[7];
    const float* W2   = (const float*)d_in[8];
    const float* b2   = (const float*)d_in[9];

    int N = in_sizes[0] / NFEAT;
    int E = in_sizes[1];
    int NBLK = (N + 1023) / 1024;
    int n2 = N * NFEAT / 2;

    __half2 *bufA, *bufB, *supp, *xh;
    unsigned* wfrag;
    int* cnt;
    cudaGetSymbolAddress((void**)&bufA,  g_bufA);
    cudaGetSymbolAddress((void**)&bufB,  g_bufB);
    cudaGetSymbolAddress((void**)&supp,  g_supph);
    cudaGetSymbolAddress((void**)&xh,    g_xh);
    cudaGetSymbolAddress((void**)&wfrag, g_wfrag);
    cudaGetSymbolAddress((void**)&cnt,   g_cnt);

    int gemmGrid = (N + 255) / 256;
    int spmmGrid = (N + 7) / 8;     // 8 warps (rows) per 256-thread block

    // front section
    cudaMemsetAsync(cnt, 0, (size_t)N * sizeof(int), 0);
    front_kernel<<<(n2 + 255) / 256, 256>>>(erow, E, x, xh, n2, W1, Wm, W2);
    hgemm_kernel<NFEAT, 8><<<gemmGrid, 256>>>((const __half*)xh, wfrag, supp, N);
    blockscan_kernel<<<NBLK, 1024>>>(N);
    bsum_scan_kernel<<<1, 128>>>(NBLK, N);
    addoff_kernel<<<(N + 255) / 256, 256>>>(N);
    scatter_kernel<<<(E + 255) / 256, 256>>>(erow, ecol, eval_, E);

    // layer 1: h1 = relu(spmm(x @ W1) + b1)            -> bufA
    spmm_kernel<NHID, 0><<<spmmGrid, 256>>>(supp, b1, nullptr, bufA, N);

    // layer 2: h2 = relu(spmm(h1 @ Wm[0]) + bm[0])     -> bufB
    hgemm_kernel<NHID, 8><<<gemmGrid, 256>>>((const __half*)bufA, wfrag + WF_WM, supp, N);
    spmm_kernel<NHID, 0><<<spmmGrid, 256>>>(supp, bm, nullptr, bufB, N);

    // middle layers k=1..NL-1: h = relu(gconv(prev)) + prev2 ; written over prev2
    __half2* prev2 = bufA;
    __half2* prev  = bufB;
    for (int k = 1; k < NL; k++) {
        hgemm_kernel<NHID, 8><<<gemmGrid, 256>>>((const __half*)prev,
                                                 wfrag + WF_WM + k * 2048, supp, N);
        spmm_kernel<NHID, 1><<<spmmGrid, 256>>>(supp, bm + (size_t)k * NHID, prev2, prev2, N);
        __half2* t = prev2; prev2 = prev; prev = t;
    }

    // final: log_softmax(spmm(prev @ W2) + b2) -> d_out  (W2 frags zero-padded to 64 cols)
    hgemm_kernel<NHID, 8><<<gemmGrid, 256>>>((const __half*)prev, wfrag + WF_W2, supp, N);
    spmm_kernel<NCLASS, 2><<<spmmGrid, 256>>>(supp, b2, nullptr, (float*)d_out, N);
}